// round 1
// baseline (speedup 1.0000x reference)
#include <cuda_runtime.h>
#include <cstdint>

#define BB      2048
#define INF     512
#define OUTF    512
#define NEXP    64
#define NTHREADS 128
#define MT      32
#define NTILE   128
#define KT      32
#define NKTILES (INF / KT)   // 16

__global__ __launch_bounds__(NTHREADS, 2)
void catlin_kernel(const float* __restrict__ x,
                   const unsigned* __restrict__ idw,
                   const float* __restrict__ weight,
                   float* __restrict__ out)
{
    __shared__ uint16_t slist[BB];
    __shared__ float Ws[2][KT * NTILE];
    __shared__ float Xs[2][KT * MT];
    __shared__ int scount;
    __shared__ unsigned sor;

    const int expert = blockIdx.x >> 2;
    const int otile  = blockIdx.x & 3;
    const int tid    = threadIdx.x;

    if (tid == 0) { scount = 0; sor = 0; }
    __syncthreads();

    // ---- dtype detection: int64 ids -> (low,0) word pairs; int32 -> raw ids.
    // Only touch the first 2048 32-bit words (in-bounds for both layouts).
    unsigned myor = 0;
    for (int i = tid; i < BB / 2; i += NTHREADS) myor |= idw[2 * i + 1];
    if (myor) atomicOr(&sor, myor);
    __syncthreads();
    const bool is64 = (sor == 0);

    // ---- compact this expert's sample list into smem
    for (int i = tid; i < BB; i += NTHREADS) {
        int id = is64 ? (int)idw[2 * i] : (int)idw[i];
        if (id == expert) {
            int p = atomicAdd(&scount, 1);
            slist[p] = (uint16_t)i;
        }
    }
    __syncthreads();
    const int m = scount;
    if (m == 0) return;   // uniform per block

    const float* wbase = weight + ((size_t)expert * OUTF + (size_t)otile * NTILE) * INF;

    const int mg = tid >> 5;    // 0..3  -> m0 = mg*8
    const int ng = tid & 31;    // 0..31 -> n0 = ng*4
    const int m0 = mg * 8;
    const int n0 = ng * 4;

    float4 wreg[8];
    float4 xreg[2];

    for (int mb = 0; mb < m; mb += MT) {
        float acc[8][4];
        #pragma unroll
        for (int i = 0; i < 8; i++)
            #pragma unroll
            for (int j = 0; j < 4; j++) acc[i][j] = 0.f;

        // ---- global -> regs (coalesced), one K-tile
        auto ldg_tile = [&](int t) {
            const int kb = t * KT;
            #pragma unroll
            for (int it = 0; it < 8; ++it) {
                int idx = it * NTHREADS + tid;   // 0..1023
                int o   = idx >> 3;              // 0..127
                int k4  = idx & 7;
                wreg[it] = *(const float4*)(wbase + (size_t)o * INF + kb + k4 * 4);
            }
            #pragma unroll
            for (int it = 0; it < 2; ++it) {
                int idx = it * NTHREADS + tid;   // 0..255
                int mr  = idx >> 3;              // 0..31
                int k4  = idx & 7;
                int row = mb + mr; if (row >= m) row = m - 1;   // pad: duplicate last
                int s   = slist[row];
                xreg[it] = *(const float4*)(x + (size_t)s * INF + kb + k4 * 4);
            }
        };

        // ---- regs -> smem, transposed to k-major with xor-swizzle.
        // W: row k = 128 floats (32 float4 cols), phys col4 = (o>>2) ^ (k>>2 & 7)
        // X: row k = 32 floats  (8 float4 cols),  phys col4 = (m>>2) ^ (k>>2 & 7)
        // Verified conflict-free for these scalar scatter stores AND the
        // vectorized compute loads.
        auto sts_tile = [&](int buf) {
            float* W = Ws[buf];
            float* X = Xs[buf];
            #pragma unroll
            for (int it = 0; it < 8; ++it) {
                int idx  = it * NTHREADS + tid;
                int o    = idx >> 3;
                int k4   = idx & 7;
                int col4 = (o >> 2) ^ k4;        // xor only low 3 bits
                float* p = W + (k4 * 4) * NTILE + col4 * 4 + (o & 3);
                p[0 * NTILE] = wreg[it].x;
                p[1 * NTILE] = wreg[it].y;
                p[2 * NTILE] = wreg[it].z;
                p[3 * NTILE] = wreg[it].w;
            }
            #pragma unroll
            for (int it = 0; it < 2; ++it) {
                int idx  = it * NTHREADS + tid;
                int mr   = idx >> 3;
                int k4   = idx & 7;
                int col4 = (mr >> 2) ^ k4;
                float* p = X + (k4 * 4) * MT + col4 * 4 + (mr & 3);
                p[0 * MT] = xreg[it].x;
                p[1 * MT] = xreg[it].y;
                p[2 * MT] = xreg[it].z;
                p[3 * MT] = xreg[it].w;
            }
        };

        auto compute = [&](int buf) {
            const float4* W4 = (const float4*)Ws[buf];
            const float4* X4 = (const float4*)Xs[buf];
            #pragma unroll
            for (int k = 0; k < KT; ++k) {
                int swz = k >> 2;                               // 0..7
                float4 wv = W4[k * (NTILE / 4) + (ng ^ swz)];   // conflict-free
                float4 xa = X4[k * (MT / 4) + ((mg * 2) ^ swz)];     // broadcast
                float4 xb = X4[k * (MT / 4) + ((mg * 2 + 1) ^ swz)]; // broadcast
                float xs[8] = {xa.x, xa.y, xa.z, xa.w, xb.x, xb.y, xb.z, xb.w};
                float ws[4] = {wv.x, wv.y, wv.z, wv.w};
                #pragma unroll
                for (int i = 0; i < 8; i++)
                    #pragma unroll
                    for (int j = 0; j < 4; j++)
                        acc[i][j] += xs[i] * ws[j];
            }
        };

        // ---- software pipeline: LDG(t+1) | compute(t) | STS(t+1) | bar
        ldg_tile(0);
        sts_tile(0);
        __syncthreads();
        for (int t = 0; t < NKTILES; ++t) {
            if (t + 1 < NKTILES) ldg_tile(t + 1);
            compute(t & 1);
            if (t + 1 < NKTILES) {
                sts_tile((t + 1) & 1);
                __syncthreads();
            }
        }

        // ---- store (coalesced 512B per m-row across the warp)
        #pragma unroll
        for (int i = 0; i < 8; ++i) {
            int row = mb + m0 + i;
            if (row < m) {
                int s = slist[row];
                float4 v = make_float4(acc[i][0], acc[i][1], acc[i][2], acc[i][3]);
                *(float4*)(out + (size_t)s * OUTF + otile * NTILE + n0) = v;
            }
        }
        __syncthreads();   // protect smem buffers before next chunk refills
    }
}

extern "C" void kernel_launch(void* const* d_in, const int* in_sizes, int n_in,
                              void* d_out, int out_size)
{
    // Map inputs by element count (robust to metadata ordering):
    // x = 2048*512 = 1048576, ids = 2048, weight = 64*512*512 = 16777216
    const float*    x   = nullptr;
    const unsigned* ids = nullptr;
    const float*    w   = nullptr;
    for (int i = 0; i < n_in; ++i) {
        if (in_sizes[i] == BB)                 ids = (const unsigned*)d_in[i];
        else if (in_sizes[i] == BB * INF)      x   = (const float*)d_in[i];
        else if (in_sizes[i] == NEXP * OUTF * INF) w = (const float*)d_in[i];
    }
    catlin_kernel<<<NEXP * 4, NTHREADS>>>(x, ids, w, (float*)d_out);
}

// round 6
// speedup vs baseline: 1.0795x; 1.0795x over previous
#include <cuda_runtime.h>
#include <cstdint>

#define BB       2048
#define INF      512
#define OUTF     512
#define NEXP     64
#define T        256
#define MT       64          // m rows per chunk (covers m<=64 in one pass)
#define NT       128         // out cols per block
#define KT       16          // k per tile
#define NTILES   (INF / KT)  // 32
#define WROW     20          // 16 k-floats + 4 pad (stride 80B -> conflict-free LDS.128)
#define XROW     16
#define NSTAGE   3

__device__ __forceinline__ void ffma2(unsigned long long &d,
                                      unsigned long long a,
                                      unsigned long long b) {
    asm("fma.rn.f32x2 %0, %1, %2, %0;" : "+l"(d) : "l"(a), "l"(b));
}

__device__ __forceinline__ void cp16(uint32_t dst, const void* src) {
    asm volatile("cp.async.ca.shared.global [%0], [%1], 16;\n"
                 :: "r"(dst), "l"(src));
}

union F2U { unsigned long long u; float f[2]; };

__global__ __launch_bounds__(T, 2)
void catlin_kernel(const float* __restrict__ x,
                   const unsigned* __restrict__ idw,
                   const float* __restrict__ weight,
                   float* __restrict__ out)
{
    __shared__ float Ws[NSTAGE][NT * WROW];   // 3*10240B
    __shared__ float Xs[NSTAGE][MT * XROW];   // 3*4096B
    __shared__ uint16_t slist[BB];            // 4096B
    __shared__ int scount;
    __shared__ unsigned sor;

    const int expert = blockIdx.x >> 2;
    const int otile  = blockIdx.x & 3;
    const int tid    = threadIdx.x;

    if (tid == 0) { scount = 0; sor = 0; }
    __syncthreads();

    // int64 vs int32 id detection (touch only first 2048 words: in-bounds either way)
    unsigned myor = 0;
    for (int i = tid; i < BB / 2; i += T) myor |= idw[2 * i + 1];
    if (myor) atomicOr(&sor, myor);
    __syncthreads();
    const bool is64 = (sor == 0);

    for (int i = tid; i < BB; i += T) {
        int id = is64 ? (int)idw[2 * i] : (int)idw[i];
        if (id == expert) {
            int p = atomicAdd(&scount, 1);
            slist[p] = (uint16_t)i;
        }
    }
    __syncthreads();
    const int m = scount;
    if (m == 0) return;

    const float* wbase = weight + ((size_t)expert * OUTF + (size_t)otile * NT) * INF;

    const int mg = tid >> 5;   // warp id 0..7 -> rows [mg*8, mg*8+8)
    const int ng = tid & 31;   // lane -> out cols {ng, ng+32, ng+64, ng+96}
    const int m0 = mg * 8;

    uint32_t wsm[NSTAGE], xsm[NSTAGE];
    #pragma unroll
    for (int b = 0; b < NSTAGE; b++) {
        wsm[b] = (uint32_t)__cvta_generic_to_shared(&Ws[b][0]);
        xsm[b] = (uint32_t)__cvta_generic_to_shared(&Xs[b][0]);
    }

    // X tile copy: 256 float4 per tile, 1 per thread
    const int x_mr = tid >> 2;
    const int x_k4 = tid & 3;

    for (int mb = 0; mb < m; mb += MT) {
        const bool active = (mb + m0) < m;

        unsigned long long acc[8][4];
        #pragma unroll
        for (int i = 0; i < 8; i++)
            #pragma unroll
            for (int j = 0; j < 4; j++) acc[i][j] = 0ULL;

        int xrow = mb + x_mr; if (xrow >= m) xrow = m - 1;   // pad: duplicate last
        const float* xsrc_row = x + (size_t)slist[xrow] * INF + x_k4 * 4;

        auto issue_tile = [&](int t) {
            const int buf = t % NSTAGE;
            const int kb  = t * KT;
            // W tile: 512 float4, 2 per thread (fully coalesced: idx = 2*tid+it)
            #pragma unroll
            for (int it = 0; it < 2; ++it) {
                int idx = 2 * tid + it;
                int o   = idx >> 2;
                int k4  = idx & 3;
                cp16(wsm[buf] + (uint32_t)(o * WROW + k4 * 4) * 4,
                     wbase + (size_t)o * INF + kb + k4 * 4);
            }
            cp16(xsm[buf] + (uint32_t)(x_mr * XROW + x_k4 * 4) * 4,
                 xsrc_row + kb);
            asm volatile("cp.async.commit_group;\n" ::);
        };

        issue_tile(0);
        issue_tile(1);

        for (int t = 0; t < NTILES; ++t) {
            if (t + 1 < NTILES) {
                asm volatile("cp.async.wait_group 1;\n" ::);
            } else {
                asm volatile("cp.async.wait_group 0;\n" ::);
            }
            __syncthreads();

            if (active) {
                const int buf = t % NSTAGE;
                const float* Wb = &Ws[buf][0];
                const float* Xb = &Xs[buf][0];
                #pragma unroll
                for (int kq = 0; kq < KT / 4; ++kq) {
                    ulonglong2 wv[4];
                    #pragma unroll
                    for (int j = 0; j < 4; ++j)
                        wv[j] = *(const ulonglong2*)(Wb + (ng + 32 * j) * WROW + kq * 4);
                    #pragma unroll
                    for (int i = 0; i < 8; ++i) {
                        ulonglong2 xv = *(const ulonglong2*)(Xb + (m0 + i) * XROW + kq * 4);
                        #pragma unroll
                        for (int j = 0; j < 4; ++j) {
                            ffma2(acc[i][j], xv.x, wv[j].x);
                            ffma2(acc[i][j], xv.y, wv[j].y);
                        }
                    }
                }
            }

            if (t + 2 < NTILES) issue_tile(t + 2);
        }

        // epilogue: per-row stores; lanes 0..31 cover 128 consecutive bytes per j
        if (active) {
            #pragma unroll
            for (int i = 0; i < 8; ++i) {
                int row = mb + m0 + i;
                if (row < m) {
                    float* obase = out + (size_t)slist[row] * OUTF + otile * NT;
                    #pragma unroll
                    for (int j = 0; j < 4; ++j) {
                        F2U u; u.u = acc[i][j];
                        obase[ng + 32 * j] = u.f[0] + u.f[1];
                    }
                }
            }
        }
        __syncthreads();   // protect smem stages before next chunk
    }
}

extern "C" void kernel_launch(void* const* d_in, const int* in_sizes, int n_in,
                              void* d_out, int out_size)
{
    const float*    x   = nullptr;
    const unsigned* ids = nullptr;
    const float*    w   = nullptr;
    for (int i = 0; i < n_in; ++i) {
        if (in_sizes[i] == BB)                     ids = (const unsigned*)d_in[i];
        else if (in_sizes[i] == BB * INF)          x   = (const float*)d_in[i];
        else if (in_sizes[i] == NEXP * OUTF * INF) w   = (const float*)d_in[i];
    }
    catlin_kernel<<<NEXP * 4, T>>>(x, ids, w, (float*)d_out);
}